// round 13
// baseline (speedup 1.0000x reference)
#include <cuda_runtime.h>
#include <cuda_bf16.h>
#include <cstdint>

#define TRACES 4096
#define LSEQ   64
#define HSZ    128
#define RBLK   64
#define PGRID  296            // persistent grid: 148 SMs x 2 CTAs

typedef unsigned int uint;

// ---- device scratch (static globals, no allocation) ----
__device__ uint2 g_fw1[3 * 16 * 4 * 32];   // [gate][ntile][k16][lane]
__device__ uint2 g_fw2[3 * 16 * 8 * 32];
__device__ uint2 g_fwp[8 * 8 * 32];
__device__ float g_trace_emb[TRACES * HSZ];
__device__ float g_partial[RBLK * HSZ];

// ---- smem byte layout (round-9 proven; stride 272 = 256 data + 16 pad) ----
#define S_X    0            // X  [64 tok][72 bf16]  stride 144B (9216B)
#define S_H1   9216         // h1 [64][136 bf16]     stride 272B (17408B)
#define S_H2   26624        // h2 [64][136 bf16]     stride 272B (17408B)
#define S_E    44032        // 64 floats
#define SMEM_BYTES 44288
#define CBUF   S_H1         // MLP contrib reuse: [64 tok][68 f32] stride 272B

__device__ __forceinline__ uint32_t smem_u32(const void* p) {
    uint32_t a;
    asm("{ .reg .u64 t; cvta.to.shared.u64 t, %1; cvt.u32.u64 %0, t; }" : "=r"(a) : "l"(p));
    return a;
}
__device__ __forceinline__ uint lds32(uint32_t a) {
    uint v; asm volatile("ld.shared.b32 %0, [%1];" : "=r"(v) : "r"(a)); return v;
}
__device__ __forceinline__ void sts32(uint32_t a, uint v) {
    asm volatile("st.shared.b32 [%0], %1;" :: "r"(a), "r"(v));
}
__device__ __forceinline__ void sts64f(uint32_t a, float x, float y) {
    asm volatile("st.shared.v2.f32 [%0], {%1, %2};" :: "r"(a), "f"(x), "f"(y));
}
__device__ __forceinline__ void ldsm4(uint r[4], uint32_t addr) {
    asm volatile("ldmatrix.sync.aligned.m8n8.x4.shared.b16 {%0,%1,%2,%3}, [%4];"
                 : "=r"(r[0]), "=r"(r[1]), "=r"(r[2]), "=r"(r[3]) : "r"(addr));
}
__device__ __forceinline__ void mma16816(float c[4], const uint a[4], uint b0, uint b1) {
    asm volatile(
        "mma.sync.aligned.m16n8k16.row.col.f32.bf16.bf16.f32 "
        "{%0,%1,%2,%3}, {%4,%5,%6,%7}, {%8,%9}, {%0,%1,%2,%3};"
        : "+f"(c[0]), "+f"(c[1]), "+f"(c[2]), "+f"(c[3])
        : "r"(a[0]), "r"(a[1]), "r"(a[2]), "r"(a[3]), "r"(b0), "r"(b1));
}
__device__ __forceinline__ float tanh_ap(float x) {
    float y; asm("tanh.approx.f32 %0, %1;" : "=f"(y) : "f"(x)); return y;
}
__device__ __forceinline__ float sigm(float x) {
    return fmaf(0.5f, tanh_ap(0.5f * x), 0.5f);
}
__device__ __forceinline__ uint pack_bf2(float a, float b) {
    __nv_bfloat162 t = __float22bfloat162_rn(make_float2(a, b));
    return *reinterpret_cast<uint*>(&t);
}

// ---------------- init: pack W into mma B-fragment layout ----------------
// B frag (m16n8k16, row.col): b0 = {B[k0][n], B[k0+1][n]}, b1 = {+8}, with
// n = ntile*8 + (lane>>2), k0 = k16*16 + (lane&3)*2.  Gate rows: i=0, c=256, o=384.
__global__ void init_frags(const float* __restrict__ W1, const float* __restrict__ W2,
                           const float* __restrict__ Wp1) {
    int idx = blockIdx.x * 256 + threadIdx.x;
    const int GR[3] = {0, 256, 384};
    if (idx < 6144) {                       // L1: [3][16][4][32], K=64
        int lane = idx & 31, k16 = (idx >> 5) & 3, nt = (idx >> 7) & 15, g = idx >> 11;
        int n = nt * 8 + (lane >> 2), k0 = k16 * 16 + (lane & 3) * 2;
        const float* r = W1 + (GR[g] + n) * 64;
        g_fw1[idx] = make_uint2(pack_bf2(r[k0], r[k0 + 1]),
                                pack_bf2(r[k0 + 8], r[k0 + 9]));
    } else if (idx < 18432) {               // L2: [3][16][8][32], K=128
        int j = idx - 6144;
        int lane = j & 31, k16 = (j >> 5) & 7, nt = (j >> 8) & 15, g = j >> 12;
        int n = nt * 8 + (lane >> 2), k0 = k16 * 16 + (lane & 3) * 2;
        const float* r = W2 + (GR[g] + n) * 128;
        g_fw2[j] = make_uint2(pack_bf2(r[k0], r[k0 + 1]),
                              pack_bf2(r[k0 + 8], r[k0 + 9]));
    } else if (idx < 20480) {               // MLP: [8][8][32], K=128, R=64
        int j = idx - 18432;
        int lane = j & 31, k16 = (j >> 5) & 7, nt = j >> 8;
        int n = nt * 8 + (lane >> 2), k0 = k16 * 16 + (lane & 3) * 2;
        const float* r = Wp1 + n * 128;
        g_fwp[j] = make_uint2(pack_bf2(r[k0], r[k0 + 1]),
                              pack_bf2(r[k0 + 8], r[k0 + 9]));
    }
}

// ---------------- fused per-trace body (round-9 proven structure) ----------------
// Warp w owns n-tiles {2w, 2w+1} (gate rows 16w..16w+15) x MT m-tiles (tokens).
template <int K16, int MT>
__device__ __forceinline__ void lstm_layer_mma(
    uint32_t inA, int istride, uint32_t outH,
    const uint2* __restrict__ frag,
    const float* __restrict__ bi, const float* __restrict__ bh,
    int w, int lane)
{
    const int gid = lane >> 2, tig = lane & 3;
    const uint32_t rowoff = (uint32_t)((lane & 15) * istride + ((lane & 16) ? 16 : 0));
    float carry[MT][2][4];

#pragma unroll
    for (int s = 0; s < 3; s++) {
        const int RB = (s == 0) ? 0 : (s == 1) ? 256 : 384;
        float acc[MT][2][4];
#pragma unroll
        for (int m = 0; m < MT; m++)
#pragma unroll
            for (int n2 = 0; n2 < 2; n2++)
#pragma unroll
                for (int j = 0; j < 4; j++) acc[m][n2][j] = 0.f;

#pragma unroll
        for (int k = 0; k < K16; k++) {
            uint a[MT][4];
#pragma unroll
            for (int m = 0; m < MT; m++)
                ldsm4(a[m], inA + (uint32_t)(m * 16 * istride + k * 32) + rowoff);
#pragma unroll
            for (int n2 = 0; n2 < 2; n2++) {
                uint2 b = __ldg(&frag[(((s * 16) + (2 * w + n2)) * K16 + k) * 32 + lane]);
#pragma unroll
                for (int m = 0; m < MT; m++) mma16816(acc[m][n2], a[m], b.x, b.y);
            }
        }

#pragma unroll
        for (int n2 = 0; n2 < 2; n2++) {
            const int col0 = (2 * w + n2) * 8 + tig * 2;
            const float b0 = bi[RB + col0] + bh[RB + col0];
            const float b1 = bi[RB + col0 + 1] + bh[RB + col0 + 1];
#pragma unroll
            for (int m = 0; m < MT; m++) {
                float v0 = acc[m][n2][0] + b0;
                float v1 = acc[m][n2][1] + b1;
                float v2 = acc[m][n2][2] + b0;
                float v3 = acc[m][n2][3] + b1;
                if (s == 0) {
                    carry[m][n2][0] = sigm(v0); carry[m][n2][1] = sigm(v1);
                    carry[m][n2][2] = sigm(v2); carry[m][n2][3] = sigm(v3);
                } else if (s == 1) {
                    carry[m][n2][0] *= tanh_ap(v0); carry[m][n2][1] *= tanh_ap(v1);
                    carry[m][n2][2] *= tanh_ap(v2); carry[m][n2][3] *= tanh_ap(v3);
                } else {
                    const int tok0 = m * 16 + gid;
                    float h0 = sigm(v0) * tanh_ap(carry[m][n2][0]);
                    float h1 = sigm(v1) * tanh_ap(carry[m][n2][1]);
                    float h2 = sigm(v2) * tanh_ap(carry[m][n2][2]);
                    float h3 = sigm(v3) * tanh_ap(carry[m][n2][3]);
                    sts32(outH + tok0 * 272 + col0 * 2, pack_bf2(h0, h1));
                    sts32(outH + (tok0 + 8) * 272 + col0 * 2, pack_bf2(h2, h3));
                }
            }
        }
    }
}

template <int MT>
__device__ __forceinline__ void trace_compute(
    char* smc, uint32_t sb, int w, int lane,
    const float* __restrict__ bi1, const float* __restrict__ bh1,
    const float* __restrict__ bi2, const float* __restrict__ bh2,
    const float* __restrict__ bp1, const float* __restrict__ wp2)
{
    const int gid = lane >> 2, tig = lane & 3;

    lstm_layer_mma<4, MT>(sb + S_X, 144, sb + S_H1, g_fw1, bi1, bh1, w, lane);
    __syncthreads();
    lstm_layer_mma<8, MT>(sb + S_H1, 272, sb + S_H2, g_fw2, bi2, bh2, w, lane);
    __syncthreads();

    // ---- MLP energy GEMM: D[MT*16 tok][64 p], warp w owns n-tile w ----
    float acc[MT][4];
#pragma unroll
    for (int m = 0; m < MT; m++)
#pragma unroll
        for (int j = 0; j < 4; j++) acc[m][j] = 0.f;
    const uint32_t rowoff = (uint32_t)((lane & 15) * 272 + ((lane & 16) ? 16 : 0));
#pragma unroll
    for (int k = 0; k < 8; k++) {
        uint a[MT][4];
#pragma unroll
        for (int m = 0; m < MT; m++)
            ldsm4(a[m], sb + S_H2 + (uint32_t)(m * 16 * 272 + k * 32) + rowoff);
        uint2 b = __ldg(&g_fwp[(w * 8 + k) * 32 + lane]);
#pragma unroll
        for (int m = 0; m < MT; m++) mma16816(acc[m], a[m], b.x, b.y);
    }
    // contrib[tok][p] = relu(v + bp1[p]) * wp2[p]  (h1 buffer reused as cbuf)
    const int p0 = w * 8 + tig * 2;
    const float bb0 = bp1[p0], bb1 = bp1[p0 + 1];
    const float w20 = wp2[p0], w21 = wp2[p0 + 1];
    __syncthreads();   // all h1 reads done
#pragma unroll
    for (int m = 0; m < MT; m++) {
        const int tok0 = m * 16 + gid;
        float v0 = fmaxf(acc[m][0] + bb0, 0.f) * w20;
        float v1 = fmaxf(acc[m][1] + bb1, 0.f) * w21;
        float v2 = fmaxf(acc[m][2] + bb0, 0.f) * w20;
        float v3 = fmaxf(acc[m][3] + bb1, 0.f) * w21;
        sts64f(sb + CBUF + tok0 * 272 + p0 * 4, v0, v1);
        sts64f(sb + CBUF + (tok0 + 8) * 272 + p0 * 4, v2, v3);
    }
}

// Persistent: each CTA loops over traces blockIdx.x + PGRID*i.
// Deterministic (static partition; each trace writes only its own rows).
__global__ __launch_bounds__(256, 2) void fused_mma_kernel(
    const float* __restrict__ emb,
    const float* __restrict__ bi1, const float* __restrict__ bh1,
    const float* __restrict__ bi2, const float* __restrict__ bh2,
    const float* __restrict__ bp1, const float* __restrict__ bp2,
    const float* __restrict__ wp2,
    const int* __restrict__ traces, const int* __restrict__ lengths)
{
    extern __shared__ char smc[];
    const int tid = threadIdx.x, w = tid >> 5, lane = tid & 31;
    const uint32_t sb = smem_u32(smc);

    for (int trace = blockIdx.x; trace < TRACES; trace += PGRID) {
        const int len = lengths[trace];
        const int mt = (len + 15) >> 4;

        // ---- gather X -> bf16 smem, only the mt*16 tokens consumed ----
        {
            int tok = tid >> 2, seg = tid & 3;
            if (tok < (mt << 4)) {
                int id = traces[trace * LSEQ + tok];
                const float4* s = (const float4*)(emb + id * 64 + seg * 16);
                float4 f0 = s[0], f1 = s[1], f2 = s[2], f3 = s[3];
                uint4 c0, c1;
                c0.x = pack_bf2(f0.x, f0.y); c0.y = pack_bf2(f0.z, f0.w);
                c0.z = pack_bf2(f1.x, f1.y); c0.w = pack_bf2(f1.z, f1.w);
                c1.x = pack_bf2(f2.x, f2.y); c1.y = pack_bf2(f2.z, f2.w);
                c1.z = pack_bf2(f3.x, f3.y); c1.w = pack_bf2(f3.z, f3.w);
                *(uint4*)(smc + S_X + tok * 144 + seg * 32) = c0;
                *(uint4*)(smc + S_X + tok * 144 + seg * 32 + 16) = c1;
            }
        }
        __syncthreads();

        // ---- length-specialized LSTM + MLP ----
        switch (mt) {
            case 1: trace_compute<1>(smc, sb, w, lane, bi1, bh1, bi2, bh2, bp1, wp2); break;
            case 2: trace_compute<2>(smc, sb, w, lane, bi1, bh1, bi2, bh2, bp1, wp2); break;
            case 3: trace_compute<3>(smc, sb, w, lane, bi1, bh1, bi2, bh2, bp1, wp2); break;
            default: trace_compute<4>(smc, sb, w, lane, bi1, bh1, bi2, bh2, bp1, wp2); break;
        }
        __syncthreads();

        // ---- energy reduce over p ----
        float* E = (float*)(smc + S_E);
        if (tid < len) {
            const float* row = (const float*)(smc + CBUF + tid * 272);
            float s = 0.f;
#pragma unroll 8
            for (int p = 0; p < 64; p++) s += row[p];
            E[tid] = s + bp2[0];
        }
        __syncthreads();

        // ---- masked softmax (warp 0) ----
        if (tid < 32) {
            float v0 = (tid      < len) ? E[tid]      : -1e30f;
            float v1 = (tid + 32 < len) ? E[tid + 32] : -1e30f;
            float mx = fmaxf(v0, v1);
#pragma unroll
            for (int o = 16; o > 0; o >>= 1) mx = fmaxf(mx, __shfl_xor_sync(~0u, mx, o));
            float e0 = __expf(v0 - mx), e1 = __expf(v1 - mx);
            float ss = e0 + e1;
#pragma unroll
            for (int o = 16; o > 0; o >>= 1) ss += __shfl_xor_sync(~0u, ss, o);
            float inv = __fdividef(1.f, ss);
            E[tid] = e0 * inv; E[tid + 32] = e1 * inv;
        }
        __syncthreads();

        // ---- weighted sum over valid positions (thread = 2 dims) ----
        if (tid < 64) {
            float ax = 0.f, ay = 0.f;
#pragma unroll 4
            for (int l = 0; l < len; l++) {
                uint hw = lds32(sb + S_H2 + l * 272 + tid * 4);
                __nv_bfloat162 hv = *reinterpret_cast<__nv_bfloat162*>(&hw);
                float e = E[l];
                ax = fmaf(e, __bfloat162float(hv.x), ax);
                ay = fmaf(e, __bfloat162float(hv.y), ay);
            }
            g_trace_emb[trace * HSZ + 2 * tid]     = ax;
            g_trace_emb[trace * HSZ + 2 * tid + 1] = ay;
        }
        __syncthreads();   // protect smem before next iteration's gather
    }
}

// ---------------- deterministic reduction + output matvec ----------------
// Stage 1: 64 blocks x 128 threads, each sums 64 traces.
__global__ __launch_bounds__(128) void reduce_part_kernel() {
    const int b = blockIdx.x, t = threadIdx.x;
    float s = 0.f;
    const int tr0 = b * (TRACES / RBLK);
#pragma unroll 8
    for (int i = 0; i < TRACES / RBLK; i++)
        s += g_trace_emb[(tr0 + i) * HSZ + t];
    g_partial[b * HSZ + t] = s;
}

// Stage 2: 1024 threads. 8 groups of 8 partials each; matvec 8 threads/row.
__global__ __launch_bounds__(1024) void reduce_out_kernel(
    const float* __restrict__ Wout, const float* __restrict__ bout,
    float* __restrict__ out)
{
    __shared__ float sq[1024];
    __shared__ float sfinal[HSZ];
    const int tid = threadIdx.x;
    const int q = tid >> 7, h = tid & 127;
    float s = 0.f;
#pragma unroll
    for (int i = 0; i < RBLK / 8; i++)
        s += g_partial[(q * (RBLK / 8) + i) * HSZ + h];
    sq[tid] = s;
    __syncthreads();
    if (tid < HSZ) {
        float t2 = 0.f;
#pragma unroll
        for (int g = 0; g < 8; g++) t2 += sq[g * 128 + tid];
        sfinal[tid] = t2;
    }
    __syncthreads();
    {   // matvec: 8 threads per output row, 16 k each
        const int r = tid >> 3, seg = tid & 7;
        float o = 0.f;
#pragma unroll
        for (int k = 0; k < 16; k++)
            o = fmaf(__ldg(&Wout[r * HSZ + seg * 16 + k]), sfinal[seg * 16 + k], o);
        o += __shfl_down_sync(0xffffffffu, o, 4, 8);
        o += __shfl_down_sync(0xffffffffu, o, 2, 8);
        o += __shfl_down_sync(0xffffffffu, o, 1, 8);
        if (seg == 0) out[r] = o + bout[r];
    }
}

extern "C" void kernel_launch(void* const* d_in, const int* in_sizes, int n_in,
                              void* d_out, int out_size) {
    const float* emb    = (const float*)d_in[0];
    const float* W1     = (const float*)d_in[1];
    const float* bi1    = (const float*)d_in[3];
    const float* bh1    = (const float*)d_in[4];
    const float* W2     = (const float*)d_in[5];
    const float* bi2    = (const float*)d_in[7];
    const float* bh2    = (const float*)d_in[8];
    const float* Wp1    = (const float*)d_in[9];
    const float* bp1    = (const float*)d_in[10];
    const float* Wp2    = (const float*)d_in[11];
    const float* bp2    = (const float*)d_in[12];
    const float* Wout   = (const float*)d_in[13];
    const float* bout   = (const float*)d_in[14];
    const int*   traces = (const int*)d_in[15];
    const int*   lens   = (const int*)d_in[16];

    cudaFuncSetAttribute(fused_mma_kernel,
                         cudaFuncAttributeMaxDynamicSharedMemorySize, SMEM_BYTES);

    init_frags<<<80, 256>>>(W1, W2, Wp1);
    fused_mma_kernel<<<PGRID, 256, SMEM_BYTES>>>(
        emb, bi1, bh1, bi2, bh2, bp1, bp2, Wp2, traces, lens);
    reduce_part_kernel<<<RBLK, 128>>>();
    reduce_out_kernel<<<1, 1024>>>(Wout, bout, (float*)d_out);
}

// round 14
// speedup vs baseline: 1.4617x; 1.4617x over previous
#include <cuda_runtime.h>
#include <cuda_bf16.h>
#include <cstdint>

#define TRACES 4096
#define LSEQ   64
#define HSZ    128

typedef unsigned int uint;

// ---- device scratch (static globals, no allocation) ----
__device__ uint2 g_fw1[3 * 16 * 4 * 32];   // [gate][ntile][k16][lane]
__device__ uint2 g_fw2[3 * 16 * 8 * 32];
__device__ uint2 g_fwp[8 * 8 * 32];
__device__ float g_trace_emb[TRACES * HSZ];

// ---- smem byte layout (round-9 proven; stride 272 = 256 data + 16 pad) ----
#define S_X    0            // X  [64 tok][72 bf16]  stride 144B (9216B)
#define S_H1   9216         // h1 [64][136 bf16]     stride 272B (17408B)
#define S_H2   26624        // h2 [64][136 bf16]     stride 272B (17408B)
#define S_E    44032        // 64 floats
#define SMEM_BYTES 44288
#define CBUF   S_H1         // MLP contrib reuse: [64 tok][68 f32] stride 272B

__device__ __forceinline__ uint32_t smem_u32(const void* p) {
    uint32_t a;
    asm("{ .reg .u64 t; cvta.to.shared.u64 t, %1; cvt.u32.u64 %0, t; }" : "=r"(a) : "l"(p));
    return a;
}
__device__ __forceinline__ uint lds32(uint32_t a) {
    uint v; asm volatile("ld.shared.b32 %0, [%1];" : "=r"(v) : "r"(a)); return v;
}
__device__ __forceinline__ void sts32(uint32_t a, uint v) {
    asm volatile("st.shared.b32 [%0], %1;" :: "r"(a), "r"(v));
}
__device__ __forceinline__ void sts64f(uint32_t a, float x, float y) {
    asm volatile("st.shared.v2.f32 [%0], {%1, %2};" :: "r"(a), "f"(x), "f"(y));
}
__device__ __forceinline__ void ldsm4(uint r[4], uint32_t addr) {
    asm volatile("ldmatrix.sync.aligned.m8n8.x4.shared.b16 {%0,%1,%2,%3}, [%4];"
                 : "=r"(r[0]), "=r"(r[1]), "=r"(r[2]), "=r"(r[3]) : "r"(addr));
}
__device__ __forceinline__ void mma16816(float c[4], const uint a[4], uint b0, uint b1) {
    asm volatile(
        "mma.sync.aligned.m16n8k16.row.col.f32.bf16.bf16.f32 "
        "{%0,%1,%2,%3}, {%4,%5,%6,%7}, {%8,%9}, {%0,%1,%2,%3};"
        : "+f"(c[0]), "+f"(c[1]), "+f"(c[2]), "+f"(c[3])
        : "r"(a[0]), "r"(a[1]), "r"(a[2]), "r"(a[3]), "r"(b0), "r"(b1));
}
__device__ __forceinline__ float tanh_ap(float x) {
    float y; asm("tanh.approx.f32 %0, %1;" : "=f"(y) : "f"(x)); return y;
}
__device__ __forceinline__ float sigm(float x) {
    return fmaf(0.5f, tanh_ap(0.5f * x), 0.5f);
}
__device__ __forceinline__ uint pack_bf2(float a, float b) {
    __nv_bfloat162 t = __float22bfloat162_rn(make_float2(a, b));
    return *reinterpret_cast<uint*>(&t);
}

// ---------------- init: pack W into mma B-fragment layout ----------------
// B frag (m16n8k16, row.col): b0 = {B[k0][n], B[k0+1][n]}, b1 = {+8}, with
// n = ntile*8 + (lane>>2), k0 = k16*16 + (lane&3)*2.  Gate rows: i=0, c=256, o=384.
__global__ void init_frags(const float* __restrict__ W1, const float* __restrict__ W2,
                           const float* __restrict__ Wp1) {
    int idx = blockIdx.x * 256 + threadIdx.x;
    const int GR[3] = {0, 256, 384};
    if (idx < 6144) {                       // L1: [3][16][4][32], K=64
        int lane = idx & 31, k16 = (idx >> 5) & 3, nt = (idx >> 7) & 15, g = idx >> 11;
        int n = nt * 8 + (lane >> 2), k0 = k16 * 16 + (lane & 3) * 2;
        const float* r = W1 + (GR[g] + n) * 64;
        g_fw1[idx] = make_uint2(pack_bf2(r[k0], r[k0 + 1]),
                                pack_bf2(r[k0 + 8], r[k0 + 9]));
    } else if (idx < 18432) {               // L2: [3][16][8][32], K=128
        int j = idx - 6144;
        int lane = j & 31, k16 = (j >> 5) & 7, nt = (j >> 8) & 15, g = j >> 12;
        int n = nt * 8 + (lane >> 2), k0 = k16 * 16 + (lane & 3) * 2;
        const float* r = W2 + (GR[g] + n) * 128;
        g_fw2[j] = make_uint2(pack_bf2(r[k0], r[k0 + 1]),
                              pack_bf2(r[k0 + 8], r[k0 + 9]));
    } else if (idx < 20480) {               // MLP: [8][8][32], K=128, R=64
        int j = idx - 18432;
        int lane = j & 31, k16 = (j >> 5) & 7, nt = j >> 8;
        int n = nt * 8 + (lane >> 2), k0 = k16 * 16 + (lane & 3) * 2;
        const float* r = Wp1 + n * 128;
        g_fwp[j] = make_uint2(pack_bf2(r[k0], r[k0 + 1]),
                              pack_bf2(r[k0 + 8], r[k0 + 9]));
    }
}

// ---------------- fused per-trace kernel (round-9 proven structure) ----------------
// Warp w owns n-tiles {2w, 2w+1} (gate rows 16w..16w+15) x MT m-tiles (tokens).
template <int K16, int MT>
__device__ __forceinline__ void lstm_layer_mma(
    uint32_t inA, int istride, uint32_t outH,
    const uint2* __restrict__ frag,
    const float* __restrict__ bi, const float* __restrict__ bh,
    int w, int lane)
{
    const int gid = lane >> 2, tig = lane & 3;
    const uint32_t rowoff = (uint32_t)((lane & 15) * istride + ((lane & 16) ? 16 : 0));
    float carry[MT][2][4];

#pragma unroll
    for (int s = 0; s < 3; s++) {
        const int RB = (s == 0) ? 0 : (s == 1) ? 256 : 384;
        float acc[MT][2][4];
#pragma unroll
        for (int m = 0; m < MT; m++)
#pragma unroll
            for (int n2 = 0; n2 < 2; n2++)
#pragma unroll
                for (int j = 0; j < 4; j++) acc[m][n2][j] = 0.f;

#pragma unroll
        for (int k = 0; k < K16; k++) {
            uint a[MT][4];
#pragma unroll
            for (int m = 0; m < MT; m++)
                ldsm4(a[m], inA + (uint32_t)(m * 16 * istride + k * 32) + rowoff);
#pragma unroll
            for (int n2 = 0; n2 < 2; n2++) {
                uint2 b = __ldg(&frag[(((s * 16) + (2 * w + n2)) * K16 + k) * 32 + lane]);
#pragma unroll
                for (int m = 0; m < MT; m++) mma16816(acc[m][n2], a[m], b.x, b.y);
            }
        }

#pragma unroll
        for (int n2 = 0; n2 < 2; n2++) {
            const int col0 = (2 * w + n2) * 8 + tig * 2;
            const float b0 = bi[RB + col0] + bh[RB + col0];
            const float b1 = bi[RB + col0 + 1] + bh[RB + col0 + 1];
#pragma unroll
            for (int m = 0; m < MT; m++) {
                float v0 = acc[m][n2][0] + b0;
                float v1 = acc[m][n2][1] + b1;
                float v2 = acc[m][n2][2] + b0;
                float v3 = acc[m][n2][3] + b1;
                if (s == 0) {
                    carry[m][n2][0] = sigm(v0); carry[m][n2][1] = sigm(v1);
                    carry[m][n2][2] = sigm(v2); carry[m][n2][3] = sigm(v3);
                } else if (s == 1) {
                    carry[m][n2][0] *= tanh_ap(v0); carry[m][n2][1] *= tanh_ap(v1);
                    carry[m][n2][2] *= tanh_ap(v2); carry[m][n2][3] *= tanh_ap(v3);
                } else {
                    const int tok0 = m * 16 + gid;
                    float h0 = sigm(v0) * tanh_ap(carry[m][n2][0]);
                    float h1 = sigm(v1) * tanh_ap(carry[m][n2][1]);
                    float h2 = sigm(v2) * tanh_ap(carry[m][n2][2]);
                    float h3 = sigm(v3) * tanh_ap(carry[m][n2][3]);
                    sts32(outH + tok0 * 272 + col0 * 2, pack_bf2(h0, h1));
                    sts32(outH + (tok0 + 8) * 272 + col0 * 2, pack_bf2(h2, h3));
                }
            }
        }
    }
}

template <int MT>
__device__ __forceinline__ void trace_compute(
    char* smc, uint32_t sb, int w, int lane,
    const float* __restrict__ bi1, const float* __restrict__ bh1,
    const float* __restrict__ bi2, const float* __restrict__ bh2,
    const float* __restrict__ bp1, const float* __restrict__ wp2)
{
    const int gid = lane >> 2, tig = lane & 3;

    lstm_layer_mma<4, MT>(sb + S_X, 144, sb + S_H1, g_fw1, bi1, bh1, w, lane);
    __syncthreads();
    lstm_layer_mma<8, MT>(sb + S_H1, 272, sb + S_H2, g_fw2, bi2, bh2, w, lane);
    __syncthreads();

    // ---- MLP energy GEMM: D[MT*16 tok][64 p], warp w owns n-tile w ----
    float acc[MT][4];
#pragma unroll
    for (int m = 0; m < MT; m++)
#pragma unroll
        for (int j = 0; j < 4; j++) acc[m][j] = 0.f;
    const uint32_t rowoff = (uint32_t)((lane & 15) * 272 + ((lane & 16) ? 16 : 0));
#pragma unroll
    for (int k = 0; k < 8; k++) {
        uint a[MT][4];
#pragma unroll
        for (int m = 0; m < MT; m++)
            ldsm4(a[m], sb + S_H2 + (uint32_t)(m * 16 * 272 + k * 32) + rowoff);
        uint2 b = __ldg(&g_fwp[(w * 8 + k) * 32 + lane]);
#pragma unroll
        for (int m = 0; m < MT; m++) mma16816(acc[m], a[m], b.x, b.y);
    }
    // contrib[tok][p] = relu(v + bp1[p]) * wp2[p]  (h1 buffer reused as cbuf)
    const int p0 = w * 8 + tig * 2;
    const float bb0 = bp1[p0], bb1 = bp1[p0 + 1];
    const float w20 = wp2[p0], w21 = wp2[p0 + 1];
    __syncthreads();   // all h1 reads done
#pragma unroll
    for (int m = 0; m < MT; m++) {
        const int tok0 = m * 16 + gid;
        float v0 = fmaxf(acc[m][0] + bb0, 0.f) * w20;
        float v1 = fmaxf(acc[m][1] + bb1, 0.f) * w21;
        float v2 = fmaxf(acc[m][2] + bb0, 0.f) * w20;
        float v3 = fmaxf(acc[m][3] + bb1, 0.f) * w21;
        sts64f(sb + CBUF + tok0 * 272 + p0 * 4, v0, v1);
        sts64f(sb + CBUF + (tok0 + 8) * 272 + p0 * 4, v2, v3);
    }
}

__global__ __launch_bounds__(256, 2) void fused_mma_kernel(
    const float* __restrict__ emb,
    const float* __restrict__ bi1, const float* __restrict__ bh1,
    const float* __restrict__ bi2, const float* __restrict__ bh2,
    const float* __restrict__ bp1, const float* __restrict__ bp2,
    const float* __restrict__ wp2,
    const int* __restrict__ traces, const int* __restrict__ lengths)
{
    extern __shared__ char smc[];
    const int tid = threadIdx.x, w = tid >> 5, lane = tid & 31;
    const int trace = blockIdx.x;
    const uint32_t sb = smem_u32(smc);
    const int len = lengths[trace];
    const int mt = (len + 15) >> 4;

    // ---- gather X -> bf16 smem, only the mt*16 tokens that get consumed ----
    {
        int tok = tid >> 2, seg = tid & 3;
        if (tok < (mt << 4)) {
            int id = traces[trace * LSEQ + tok];
            const float4* s = (const float4*)(emb + id * 64 + seg * 16);
            float4 f0 = s[0], f1 = s[1], f2 = s[2], f3 = s[3];
            uint4 c0, c1;
            c0.x = pack_bf2(f0.x, f0.y); c0.y = pack_bf2(f0.z, f0.w);
            c0.z = pack_bf2(f1.x, f1.y); c0.w = pack_bf2(f1.z, f1.w);
            c1.x = pack_bf2(f2.x, f2.y); c1.y = pack_bf2(f2.z, f2.w);
            c1.z = pack_bf2(f3.x, f3.y); c1.w = pack_bf2(f3.z, f3.w);
            *(uint4*)(smc + S_X + tok * 144 + seg * 32) = c0;
            *(uint4*)(smc + S_X + tok * 144 + seg * 32 + 16) = c1;
        }
    }
    __syncthreads();

    // ---- length-specialized LSTM + MLP (only m-tiles covering len) ----
    switch (mt) {
        case 1: trace_compute<1>(smc, sb, w, lane, bi1, bh1, bi2, bh2, bp1, wp2); break;
        case 2: trace_compute<2>(smc, sb, w, lane, bi1, bh1, bi2, bh2, bp1, wp2); break;
        case 3: trace_compute<3>(smc, sb, w, lane, bi1, bh1, bi2, bh2, bp1, wp2); break;
        default: trace_compute<4>(smc, sb, w, lane, bi1, bh1, bi2, bh2, bp1, wp2); break;
    }
    __syncthreads();

    // ---- energy reduce over p (only valid tokens needed) ----
    float* E = (float*)(smc + S_E);
    if (tid < len) {
        const float* row = (const float*)(smc + CBUF + tid * 272);
        float s = 0.f;
#pragma unroll 8
        for (int p = 0; p < 64; p++) s += row[p];
        E[tid] = s + bp2[0];
    }
    __syncthreads();

    // ---- masked softmax (warp 0) ----
    if (tid < 32) {
        float v0 = (tid      < len) ? E[tid]      : -1e30f;
        float v1 = (tid + 32 < len) ? E[tid + 32] : -1e30f;
        float mx = fmaxf(v0, v1);
#pragma unroll
        for (int o = 16; o > 0; o >>= 1) mx = fmaxf(mx, __shfl_xor_sync(~0u, mx, o));
        float e0 = __expf(v0 - mx), e1 = __expf(v1 - mx);
        float ss = e0 + e1;
#pragma unroll
        for (int o = 16; o > 0; o >>= 1) ss += __shfl_xor_sync(~0u, ss, o);
        float inv = __fdividef(1.f, ss);
        E[tid] = e0 * inv; E[tid + 32] = e1 * inv;
    }
    __syncthreads();

    // ---- weighted sum over valid positions (thread = 2 dims, bf16x2 word) ----
    if (tid < 64) {
        float ax = 0.f, ay = 0.f;
#pragma unroll 4
        for (int l = 0; l < len; l++) {
            uint hw = lds32(sb + S_H2 + l * 272 + tid * 4);
            __nv_bfloat162 hv = *reinterpret_cast<__nv_bfloat162*>(&hw);
            float e = E[l];
            ax = fmaf(e, __bfloat162float(hv.x), ax);
            ay = fmaf(e, __bfloat162float(hv.y), ay);
        }
        g_trace_emb[trace * HSZ + 2 * tid]     = ax;
        g_trace_emb[trace * HSZ + 2 * tid + 1] = ay;
    }
}

// ---------------- single-block deterministic reduction + output matvec ----------------
// 1024 threads = 32 groups x 32 float4-lanes. Group g serially sums traces
// [g*128, (g+1)*128) with 2 interleaved accumulators (fixed order), combine
// via smem, then matvec with 8 threads per output row.
__global__ __launch_bounds__(1024) void reduce_all_kernel(
    const float* __restrict__ Wout, const float* __restrict__ bout,
    float* __restrict__ out)
{
    __shared__ float4 sq[32][33];     // [group][c4], padded
    __shared__ float sfinal[HSZ];
    const int tid = threadIdx.x;
    const int c4 = tid & 31, g = tid >> 5;
    const float4* te = (const float4*)g_trace_emb;   // [trace][32] float4

    float4 s0 = make_float4(0.f, 0.f, 0.f, 0.f);
    float4 s1 = make_float4(0.f, 0.f, 0.f, 0.f);
#pragma unroll 8
    for (int i = 0; i < 128; i += 2) {
        float4 a = __ldg(&te[(g * 128 + i) * 32 + c4]);
        float4 b = __ldg(&te[(g * 128 + i + 1) * 32 + c4]);
        s0.x += a.x; s0.y += a.y; s0.z += a.z; s0.w += a.w;
        s1.x += b.x; s1.y += b.y; s1.z += b.z; s1.w += b.w;
    }
    s0.x += s1.x; s0.y += s1.y; s0.z += s1.z; s0.w += s1.w;
    sq[g][c4] = s0;
    __syncthreads();

    if (tid < 32) {                    // combine 32 groups per float4 chunk
        float4 t = make_float4(0.f, 0.f, 0.f, 0.f);
#pragma unroll
        for (int gg = 0; gg < 32; gg++) {
            float4 v = sq[gg][tid];
            t.x += v.x; t.y += v.y; t.z += v.z; t.w += v.w;
        }
        sfinal[tid * 4 + 0] = t.x;
        sfinal[tid * 4 + 1] = t.y;
        sfinal[tid * 4 + 2] = t.z;
        sfinal[tid * 4 + 3] = t.w;
    }
    __syncthreads();

    {   // matvec: 8 threads per output row, 16 k each
        const int r = tid >> 3, seg = tid & 7;
        float o = 0.f;
#pragma unroll
        for (int k = 0; k < 16; k++)
            o = fmaf(__ldg(&Wout[r * HSZ + seg * 16 + k]), sfinal[seg * 16 + k], o);
        o += __shfl_down_sync(0xffffffffu, o, 4, 8);
        o += __shfl_down_sync(0xffffffffu, o, 2, 8);
        o += __shfl_down_sync(0xffffffffu, o, 1, 8);
        if (seg == 0) out[r] = o + bout[r];
    }
}

extern "C" void kernel_launch(void* const* d_in, const int* in_sizes, int n_in,
                              void* d_out, int out_size) {
    const float* emb    = (const float*)d_in[0];
    const float* W1     = (const float*)d_in[1];
    const float* bi1    = (const float*)d_in[3];
    const float* bh1    = (const float*)d_in[4];
    const float* W2     = (const float*)d_in[5];
    const float* bi2    = (const float*)d_in[7];
    const float* bh2    = (const float*)d_in[8];
    const float* Wp1    = (const float*)d_in[9];
    const float* bp1    = (const float*)d_in[10];
    const float* Wp2    = (const float*)d_in[11];
    const float* bp2    = (const float*)d_in[12];
    const float* Wout   = (const float*)d_in[13];
    const float* bout   = (const float*)d_in[14];
    const int*   traces = (const int*)d_in[15];
    const int*   lens   = (const int*)d_in[16];

    cudaFuncSetAttribute(fused_mma_kernel,
                         cudaFuncAttributeMaxDynamicSharedMemorySize, SMEM_BYTES);

    init_frags<<<80, 256>>>(W1, W2, Wp1);
    fused_mma_kernel<<<TRACES, 256, SMEM_BYTES>>>(
        emb, bi1, bh1, bi2, bh2, bp1, bp2, Wp2, traces, lens);
    reduce_all_kernel<<<1, 1024>>>(Wout, bout, (float*)d_out);
}

// round 15
// speedup vs baseline: 1.5207x; 1.0404x over previous
#include <cuda_runtime.h>
#include <cuda_bf16.h>
#include <cstdint>

#define TRACES 4096
#define LSEQ   64
#define HSZ    128
#define RBLK   128

typedef unsigned int uint;

// ---- device scratch (static globals, no allocation) ----
__device__ uint2 g_fw1[3 * 16 * 4 * 32];   // [gate][ntile][k16][lane]
__device__ uint2 g_fw2[3 * 16 * 8 * 32];
__device__ uint2 g_fwp[8 * 8 * 32];
__device__ float g_trace_emb[TRACES * HSZ];
__device__ float g_partial[RBLK * HSZ];
__device__ int   g_count;                  // tail rendezvous (self-resetting)

// ---- smem byte layout (round-9 proven; stride 272 = 256 data + 16 pad) ----
#define S_X    0            // X  [64 tok][72 bf16]  stride 144B (9216B)
#define S_H1   9216         // h1 [64][136 bf16]     stride 272B (17408B)
#define S_H2   26624        // h2 [64][136 bf16]     stride 272B (17408B)
#define S_E    44032        // 64 floats
#define SMEM_BYTES 44288
#define CBUF   S_H1         // MLP contrib reuse: [64 tok][68 f32] stride 272B

__device__ __forceinline__ uint32_t smem_u32(const void* p) {
    uint32_t a;
    asm("{ .reg .u64 t; cvta.to.shared.u64 t, %1; cvt.u32.u64 %0, t; }" : "=r"(a) : "l"(p));
    return a;
}
__device__ __forceinline__ uint lds32(uint32_t a) {
    uint v; asm volatile("ld.shared.b32 %0, [%1];" : "=r"(v) : "r"(a)); return v;
}
__device__ __forceinline__ void sts32(uint32_t a, uint v) {
    asm volatile("st.shared.b32 [%0], %1;" :: "r"(a), "r"(v));
}
__device__ __forceinline__ void sts64f(uint32_t a, float x, float y) {
    asm volatile("st.shared.v2.f32 [%0], {%1, %2};" :: "r"(a), "f"(x), "f"(y));
}
__device__ __forceinline__ void ldsm4(uint r[4], uint32_t addr) {
    asm volatile("ldmatrix.sync.aligned.m8n8.x4.shared.b16 {%0,%1,%2,%3}, [%4];"
                 : "=r"(r[0]), "=r"(r[1]), "=r"(r[2]), "=r"(r[3]) : "r"(addr));
}
__device__ __forceinline__ void mma16816(float c[4], const uint a[4], uint b0, uint b1) {
    asm volatile(
        "mma.sync.aligned.m16n8k16.row.col.f32.bf16.bf16.f32 "
        "{%0,%1,%2,%3}, {%4,%5,%6,%7}, {%8,%9}, {%0,%1,%2,%3};"
        : "+f"(c[0]), "+f"(c[1]), "+f"(c[2]), "+f"(c[3])
        : "r"(a[0]), "r"(a[1]), "r"(a[2]), "r"(a[3]), "r"(b0), "r"(b1));
}
__device__ __forceinline__ float tanh_ap(float x) {
    float y; asm("tanh.approx.f32 %0, %1;" : "=f"(y) : "f"(x)); return y;
}
__device__ __forceinline__ float sigm(float x) {
    return fmaf(0.5f, tanh_ap(0.5f * x), 0.5f);
}
__device__ __forceinline__ uint pack_bf2(float a, float b) {
    __nv_bfloat162 t = __float22bfloat162_rn(make_float2(a, b));
    return *reinterpret_cast<uint*>(&t);
}

// ---------------- init: pack W into mma B-fragment layout ----------------
// B frag (m16n8k16, row.col): b0 = {B[k0][n], B[k0+1][n]}, b1 = {+8}, with
// n = ntile*8 + (lane>>2), k0 = k16*16 + (lane&3)*2.  Gate rows: i=0, c=256, o=384.
__global__ void init_frags(const float* __restrict__ W1, const float* __restrict__ W2,
                           const float* __restrict__ Wp1) {
    int idx = blockIdx.x * 256 + threadIdx.x;
    const int GR[3] = {0, 256, 384};
    if (idx < 6144) {                       // L1: [3][16][4][32], K=64
        int lane = idx & 31, k16 = (idx >> 5) & 3, nt = (idx >> 7) & 15, g = idx >> 11;
        int n = nt * 8 + (lane >> 2), k0 = k16 * 16 + (lane & 3) * 2;
        const float* r = W1 + (GR[g] + n) * 64;
        g_fw1[idx] = make_uint2(pack_bf2(r[k0], r[k0 + 1]),
                                pack_bf2(r[k0 + 8], r[k0 + 9]));
    } else if (idx < 18432) {               // L2: [3][16][8][32], K=128
        int j = idx - 6144;
        int lane = j & 31, k16 = (j >> 5) & 7, nt = (j >> 8) & 15, g = j >> 12;
        int n = nt * 8 + (lane >> 2), k0 = k16 * 16 + (lane & 3) * 2;
        const float* r = W2 + (GR[g] + n) * 128;
        g_fw2[j] = make_uint2(pack_bf2(r[k0], r[k0 + 1]),
                              pack_bf2(r[k0 + 8], r[k0 + 9]));
    } else if (idx < 20480) {               // MLP: [8][8][32], K=128, R=64
        int j = idx - 18432;
        int lane = j & 31, k16 = (j >> 5) & 7, nt = j >> 8;
        int n = nt * 8 + (lane >> 2), k0 = k16 * 16 + (lane & 3) * 2;
        const float* r = Wp1 + n * 128;
        g_fwp[j] = make_uint2(pack_bf2(r[k0], r[k0 + 1]),
                              pack_bf2(r[k0 + 8], r[k0 + 9]));
    }
}

// ---------------- fused per-trace kernel (round-9 proven structure) ----------------
// Warp w owns n-tiles {2w, 2w+1} (gate rows 16w..16w+15) x MT m-tiles (tokens).
template <int K16, int MT>
__device__ __forceinline__ void lstm_layer_mma(
    uint32_t inA, int istride, uint32_t outH,
    const uint2* __restrict__ frag,
    const float* __restrict__ bi, const float* __restrict__ bh,
    int w, int lane)
{
    const int gid = lane >> 2, tig = lane & 3;
    const uint32_t rowoff = (uint32_t)((lane & 15) * istride + ((lane & 16) ? 16 : 0));
    float carry[MT][2][4];

#pragma unroll
    for (int s = 0; s < 3; s++) {
        const int RB = (s == 0) ? 0 : (s == 1) ? 256 : 384;
        float acc[MT][2][4];
#pragma unroll
        for (int m = 0; m < MT; m++)
#pragma unroll
            for (int n2 = 0; n2 < 2; n2++)
#pragma unroll
                for (int j = 0; j < 4; j++) acc[m][n2][j] = 0.f;

#pragma unroll
        for (int k = 0; k < K16; k++) {
            uint a[MT][4];
#pragma unroll
            for (int m = 0; m < MT; m++)
                ldsm4(a[m], inA + (uint32_t)(m * 16 * istride + k * 32) + rowoff);
#pragma unroll
            for (int n2 = 0; n2 < 2; n2++) {
                uint2 b = __ldg(&frag[(((s * 16) + (2 * w + n2)) * K16 + k) * 32 + lane]);
#pragma unroll
                for (int m = 0; m < MT; m++) mma16816(acc[m][n2], a[m], b.x, b.y);
            }
        }

#pragma unroll
        for (int n2 = 0; n2 < 2; n2++) {
            const int col0 = (2 * w + n2) * 8 + tig * 2;
            const float b0 = bi[RB + col0] + bh[RB + col0];
            const float b1 = bi[RB + col0 + 1] + bh[RB + col0 + 1];
#pragma unroll
            for (int m = 0; m < MT; m++) {
                float v0 = acc[m][n2][0] + b0;
                float v1 = acc[m][n2][1] + b1;
                float v2 = acc[m][n2][2] + b0;
                float v3 = acc[m][n2][3] + b1;
                if (s == 0) {
                    carry[m][n2][0] = sigm(v0); carry[m][n2][1] = sigm(v1);
                    carry[m][n2][2] = sigm(v2); carry[m][n2][3] = sigm(v3);
                } else if (s == 1) {
                    carry[m][n2][0] *= tanh_ap(v0); carry[m][n2][1] *= tanh_ap(v1);
                    carry[m][n2][2] *= tanh_ap(v2); carry[m][n2][3] *= tanh_ap(v3);
                } else {
                    const int tok0 = m * 16 + gid;
                    float h0 = sigm(v0) * tanh_ap(carry[m][n2][0]);
                    float h1 = sigm(v1) * tanh_ap(carry[m][n2][1]);
                    float h2 = sigm(v2) * tanh_ap(carry[m][n2][2]);
                    float h3 = sigm(v3) * tanh_ap(carry[m][n2][3]);
                    sts32(outH + tok0 * 272 + col0 * 2, pack_bf2(h0, h1));
                    sts32(outH + (tok0 + 8) * 272 + col0 * 2, pack_bf2(h2, h3));
                }
            }
        }
    }
}

template <int MT>
__device__ __forceinline__ void trace_compute(
    char* smc, uint32_t sb, int w, int lane,
    const float* __restrict__ bi1, const float* __restrict__ bh1,
    const float* __restrict__ bi2, const float* __restrict__ bh2,
    const float* __restrict__ bp1, const float* __restrict__ wp2)
{
    const int gid = lane >> 2, tig = lane & 3;

    lstm_layer_mma<4, MT>(sb + S_X, 144, sb + S_H1, g_fw1, bi1, bh1, w, lane);
    __syncthreads();
    lstm_layer_mma<8, MT>(sb + S_H1, 272, sb + S_H2, g_fw2, bi2, bh2, w, lane);
    __syncthreads();

    // ---- MLP energy GEMM: D[MT*16 tok][64 p], warp w owns n-tile w ----
    float acc[MT][4];
#pragma unroll
    for (int m = 0; m < MT; m++)
#pragma unroll
        for (int j = 0; j < 4; j++) acc[m][j] = 0.f;
    const uint32_t rowoff = (uint32_t)((lane & 15) * 272 + ((lane & 16) ? 16 : 0));
#pragma unroll
    for (int k = 0; k < 8; k++) {
        uint a[MT][4];
#pragma unroll
        for (int m = 0; m < MT; m++)
            ldsm4(a[m], sb + S_H2 + (uint32_t)(m * 16 * 272 + k * 32) + rowoff);
        uint2 b = __ldg(&g_fwp[(w * 8 + k) * 32 + lane]);
#pragma unroll
        for (int m = 0; m < MT; m++) mma16816(acc[m], a[m], b.x, b.y);
    }
    // contrib[tok][p] = relu(v + bp1[p]) * wp2[p]  (h1 buffer reused as cbuf)
    const int p0 = w * 8 + tig * 2;
    const float bb0 = bp1[p0], bb1 = bp1[p0 + 1];
    const float w20 = wp2[p0], w21 = wp2[p0 + 1];
    __syncthreads();   // all h1 reads done
#pragma unroll
    for (int m = 0; m < MT; m++) {
        const int tok0 = m * 16 + gid;
        float v0 = fmaxf(acc[m][0] + bb0, 0.f) * w20;
        float v1 = fmaxf(acc[m][1] + bb1, 0.f) * w21;
        float v2 = fmaxf(acc[m][2] + bb0, 0.f) * w20;
        float v3 = fmaxf(acc[m][3] + bb1, 0.f) * w21;
        sts64f(sb + CBUF + tok0 * 272 + p0 * 4, v0, v1);
        sts64f(sb + CBUF + (tok0 + 8) * 272 + p0 * 4, v2, v3);
    }
}

__global__ __launch_bounds__(256, 2) void fused_mma_kernel(
    const float* __restrict__ emb,
    const float* __restrict__ bi1, const float* __restrict__ bh1,
    const float* __restrict__ bi2, const float* __restrict__ bh2,
    const float* __restrict__ bp1, const float* __restrict__ bp2,
    const float* __restrict__ wp2,
    const int* __restrict__ traces, const int* __restrict__ lengths)
{
    extern __shared__ char smc[];
    const int tid = threadIdx.x, w = tid >> 5, lane = tid & 31;
    const int trace = blockIdx.x;
    const uint32_t sb = smem_u32(smc);
    const int len = lengths[trace];
    const int mt = (len + 15) >> 4;

    // ---- gather X -> bf16 smem, only the mt*16 tokens that get consumed ----
    {
        int tok = tid >> 2, seg = tid & 3;
        if (tok < (mt << 4)) {
            int id = traces[trace * LSEQ + tok];
            const float4* s = (const float4*)(emb + id * 64 + seg * 16);
            float4 f0 = s[0], f1 = s[1], f2 = s[2], f3 = s[3];
            uint4 c0, c1;
            c0.x = pack_bf2(f0.x, f0.y); c0.y = pack_bf2(f0.z, f0.w);
            c0.z = pack_bf2(f1.x, f1.y); c0.w = pack_bf2(f1.z, f1.w);
            c1.x = pack_bf2(f2.x, f2.y); c1.y = pack_bf2(f2.z, f2.w);
            c1.z = pack_bf2(f3.x, f3.y); c1.w = pack_bf2(f3.z, f3.w);
            *(uint4*)(smc + S_X + tok * 144 + seg * 32) = c0;
            *(uint4*)(smc + S_X + tok * 144 + seg * 32 + 16) = c1;
        }
    }
    __syncthreads();

    // ---- length-specialized LSTM + MLP (only m-tiles covering len) ----
    switch (mt) {
        case 1: trace_compute<1>(smc, sb, w, lane, bi1, bh1, bi2, bh2, bp1, wp2); break;
        case 2: trace_compute<2>(smc, sb, w, lane, bi1, bh1, bi2, bh2, bp1, wp2); break;
        case 3: trace_compute<3>(smc, sb, w, lane, bi1, bh1, bi2, bh2, bp1, wp2); break;
        default: trace_compute<4>(smc, sb, w, lane, bi1, bh1, bi2, bh2, bp1, wp2); break;
    }
    __syncthreads();

    // ---- energy reduce over p (only valid tokens needed) ----
    float* E = (float*)(smc + S_E);
    if (tid < len) {
        const float* row = (const float*)(smc + CBUF + tid * 272);
        float s = 0.f;
#pragma unroll 8
        for (int p = 0; p < 64; p++) s += row[p];
        E[tid] = s + bp2[0];
    }
    __syncthreads();

    // ---- masked softmax (warp 0) ----
    if (tid < 32) {
        float v0 = (tid      < len) ? E[tid]      : -1e30f;
        float v1 = (tid + 32 < len) ? E[tid + 32] : -1e30f;
        float mx = fmaxf(v0, v1);
#pragma unroll
        for (int o = 16; o > 0; o >>= 1) mx = fmaxf(mx, __shfl_xor_sync(~0u, mx, o));
        float e0 = __expf(v0 - mx), e1 = __expf(v1 - mx);
        float ss = e0 + e1;
#pragma unroll
        for (int o = 16; o > 0; o >>= 1) ss += __shfl_xor_sync(~0u, ss, o);
        float inv = __fdividef(1.f, ss);
        E[tid] = e0 * inv; E[tid + 32] = e1 * inv;
    }
    __syncthreads();

    // ---- weighted sum over valid positions (thread = 2 dims, bf16x2 word) ----
    if (tid < 64) {
        float ax = 0.f, ay = 0.f;
#pragma unroll 4
        for (int l = 0; l < len; l++) {
            uint hw = lds32(sb + S_H2 + l * 272 + tid * 4);
            __nv_bfloat162 hv = *reinterpret_cast<__nv_bfloat162*>(&hw);
            float e = E[l];
            ax = fmaf(e, __bfloat162float(hv.x), ax);
            ay = fmaf(e, __bfloat162float(hv.y), ay);
        }
        g_trace_emb[trace * HSZ + 2 * tid]     = ax;
        g_trace_emb[trace * HSZ + 2 * tid + 1] = ay;
    }
}

// ---------------- single-launch tail: 128-block partials + last-block matvec ----
// Deterministic: fixed partition, fixed-order sums; the atomic only selects
// WHICH block finishes the (order-independent per-element) final combine.
__global__ __launch_bounds__(128) void reduce_tail_kernel(
    const float* __restrict__ Wout, const float* __restrict__ bout,
    float* __restrict__ out)
{
    __shared__ float sfinal[HSZ];
    __shared__ int is_last;
    const int b = blockIdx.x, t = threadIdx.x;

    float s = 0.f;
    const int tr0 = b * (TRACES / RBLK);
#pragma unroll
    for (int i = 0; i < TRACES / RBLK; i++)
        s += g_trace_emb[(tr0 + i) * HSZ + t];
    g_partial[b * HSZ + t] = s;

    __threadfence();
    __syncthreads();
    if (t == 0) is_last = (atomicAdd(&g_count, 1) == RBLK - 1) ? 1 : 0;
    __syncthreads();
    if (!is_last) return;
    if (t == 0) g_count = 0;     // self-reset for next graph replay

    float t2 = 0.f;
#pragma unroll 16
    for (int g = 0; g < RBLK; g++) t2 += g_partial[g * HSZ + t];
    sfinal[t] = t2;
    __syncthreads();

    float o = bout[t];
#pragma unroll 8
    for (int k = 0; k < HSZ; k++)
        o = fmaf(__ldg(&Wout[t * HSZ + k]), sfinal[k], o);
    out[t] = o;
}

extern "C" void kernel_launch(void* const* d_in, const int* in_sizes, int n_in,
                              void* d_out, int out_size) {
    const float* emb    = (const float*)d_in[0];
    const float* W1     = (const float*)d_in[1];
    const float* bi1    = (const float*)d_in[3];
    const float* bh1    = (const float*)d_in[4];
    const float* W2     = (const float*)d_in[5];
    const float* bi2    = (const float*)d_in[7];
    const float* bh2    = (const float*)d_in[8];
    const float* Wp1    = (const float*)d_in[9];
    const float* bp1    = (const float*)d_in[10];
    const float* Wp2    = (const float*)d_in[11];
    const float* bp2    = (const float*)d_in[12];
    const float* Wout   = (const float*)d_in[13];
    const float* bout   = (const float*)d_in[14];
    const int*   traces = (const int*)d_in[15];
    const int*   lens   = (const int*)d_in[16];

    cudaFuncSetAttribute(fused_mma_kernel,
                         cudaFuncAttributeMaxDynamicSharedMemorySize, SMEM_BYTES);

    init_frags<<<80, 256>>>(W1, W2, Wp1);
    fused_mma_kernel<<<TRACES, 256, SMEM_BYTES>>>(
        emb, bi1, bh1, bi2, bh2, bp1, bp2, Wp2, traces, lens);
    reduce_tail_kernel<<<RBLK, 128>>>(Wout, bout, (float*)d_out);
}

// round 16
// speedup vs baseline: 1.5524x; 1.0209x over previous
#include <cuda_runtime.h>
#include <cuda_bf16.h>
#include <cstdint>

#define TRACES 4096
#define LSEQ   64
#define HSZ    128
#define RBLK   64

typedef unsigned int uint;

// ---- device scratch (static globals, no allocation) ----
__device__ uint2 g_fw1[3 * 16 * 4 * 32];   // [gate][ntile][k16][lane]
__device__ uint2 g_fw2[3 * 16 * 8 * 32];
__device__ uint2 g_fwp[8 * 8 * 32];
__device__ float g_trace_emb[TRACES * HSZ];
__device__ float g_partial[RBLK * HSZ];
__device__ int   g_perm[TRACES];           // mt-descending schedule

// ---- smem byte layout (round-9 proven; stride 272 = 256 data + 16 pad) ----
#define S_X    0            // X  [64 tok][72 bf16]  stride 144B (9216B)
#define S_H1   9216         // h1 [64][136 bf16]     stride 272B (17408B)
#define S_H2   26624        // h2 [64][136 bf16]     stride 272B (17408B)
#define S_E    44032        // 64 floats
#define SMEM_BYTES 44288
#define CBUF   S_H1         // MLP contrib reuse: [64 tok][68 f32] stride 272B

__device__ __forceinline__ uint32_t smem_u32(const void* p) {
    uint32_t a;
    asm("{ .reg .u64 t; cvta.to.shared.u64 t, %1; cvt.u32.u64 %0, t; }" : "=r"(a) : "l"(p));
    return a;
}
__device__ __forceinline__ uint lds32(uint32_t a) {
    uint v; asm volatile("ld.shared.b32 %0, [%1];" : "=r"(v) : "r"(a)); return v;
}
__device__ __forceinline__ void sts32(uint32_t a, uint v) {
    asm volatile("st.shared.b32 [%0], %1;" :: "r"(a), "r"(v));
}
__device__ __forceinline__ void sts64f(uint32_t a, float x, float y) {
    asm volatile("st.shared.v2.f32 [%0], {%1, %2};" :: "r"(a), "f"(x), "f"(y));
}
__device__ __forceinline__ void ldsm4(uint r[4], uint32_t addr) {
    asm volatile("ldmatrix.sync.aligned.m8n8.x4.shared.b16 {%0,%1,%2,%3}, [%4];"
                 : "=r"(r[0]), "=r"(r[1]), "=r"(r[2]), "=r"(r[3]) : "r"(addr));
}
__device__ __forceinline__ void mma16816(float c[4], const uint a[4], uint b0, uint b1) {
    asm volatile(
        "mma.sync.aligned.m16n8k16.row.col.f32.bf16.bf16.f32 "
        "{%0,%1,%2,%3}, {%4,%5,%6,%7}, {%8,%9}, {%0,%1,%2,%3};"
        : "+f"(c[0]), "+f"(c[1]), "+f"(c[2]), "+f"(c[3])
        : "r"(a[0]), "r"(a[1]), "r"(a[2]), "r"(a[3]), "r"(b0), "r"(b1));
}
__device__ __forceinline__ float tanh_ap(float x) {
    float y; asm("tanh.approx.f32 %0, %1;" : "=f"(y) : "f"(x)); return y;
}
__device__ __forceinline__ float sigm(float x) {
    return fmaf(0.5f, tanh_ap(0.5f * x), 0.5f);
}
__device__ __forceinline__ uint pack_bf2(float a, float b) {
    __nv_bfloat162 t = __float22bfloat162_rn(make_float2(a, b));
    return *reinterpret_cast<uint*>(&t);
}

// ---------------- init: pack W into mma B-fragment layout + build schedule ----
// Blocks 0..79: fragment packing (round-9 layout).
// Block 80: deterministic counting sort of traces by mt DESCENDING (stable).
__global__ void init_frags(const float* __restrict__ W1, const float* __restrict__ W2,
                           const float* __restrict__ Wp1,
                           const int* __restrict__ lengths) {
    if (blockIdx.x == 80) {
        // ---- stable counting sort: bins mt-1 in {0,1,2,3}, order mt=4 first ----
        __shared__ int sc[4][256];
        const int t = threadIdx.x;
        int lc[4] = {0, 0, 0, 0};
        int mts[16];
#pragma unroll
        for (int i = 0; i < 16; i++) {
            int tr = t * 16 + i;
            int mt = (lengths[tr] + 15) >> 4;     // 1..4
            mts[i] = mt - 1;
            lc[mt - 1]++;
        }
#pragma unroll
        for (int b = 0; b < 4; b++) sc[b][t] = lc[b];
        __syncthreads();
        for (int off = 1; off < 256; off <<= 1) {   // inclusive scan over threads
            int v[4];
#pragma unroll
            for (int b = 0; b < 4; b++) v[b] = (t >= off) ? sc[b][t - off] : 0;
            __syncthreads();
#pragma unroll
            for (int b = 0; b < 4; b++) sc[b][t] += v[b];
            __syncthreads();
        }
        int tot[4];
#pragma unroll
        for (int b = 0; b < 4; b++) tot[b] = sc[b][255];
        // descending-mt bin bases: bin3 (mt=4) first
        int base[4];
        base[3] = 0;
        base[2] = tot[3];
        base[1] = tot[3] + tot[2];
        base[0] = tot[3] + tot[2] + tot[1];
        int start[4];
#pragma unroll
        for (int b = 0; b < 4; b++) start[b] = base[b] + sc[b][t] - lc[b];
#pragma unroll
        for (int i = 0; i < 16; i++) {
            int b = mts[i];
            g_perm[start[b]++] = t * 16 + i;
        }
        return;
    }

    int idx = blockIdx.x * 256 + threadIdx.x;
    const int GR[3] = {0, 256, 384};
    if (idx < 6144) {                       // L1: [3][16][4][32], K=64
        int lane = idx & 31, k16 = (idx >> 5) & 3, nt = (idx >> 7) & 15, g = idx >> 11;
        int n = nt * 8 + (lane >> 2), k0 = k16 * 16 + (lane & 3) * 2;
        const float* r = W1 + (GR[g] + n) * 64;
        g_fw1[idx] = make_uint2(pack_bf2(r[k0], r[k0 + 1]),
                                pack_bf2(r[k0 + 8], r[k0 + 9]));
    } else if (idx < 18432) {               // L2: [3][16][8][32], K=128
        int j = idx - 6144;
        int lane = j & 31, k16 = (j >> 5) & 7, nt = (j >> 8) & 15, g = j >> 12;
        int n = nt * 8 + (lane >> 2), k0 = k16 * 16 + (lane & 3) * 2;
        const float* r = W2 + (GR[g] + n) * 128;
        g_fw2[j] = make_uint2(pack_bf2(r[k0], r[k0 + 1]),
                              pack_bf2(r[k0 + 8], r[k0 + 9]));
    } else if (idx < 20480) {               // MLP: [8][8][32], K=128, R=64
        int j = idx - 18432;
        int lane = j & 31, k16 = (j >> 5) & 7, nt = j >> 8;
        int n = nt * 8 + (lane >> 2), k0 = k16 * 16 + (lane & 3) * 2;
        const float* r = Wp1 + n * 128;
        g_fwp[j] = make_uint2(pack_bf2(r[k0], r[k0 + 1]),
                              pack_bf2(r[k0 + 8], r[k0 + 9]));
    }
}

// ---------------- fused per-trace kernel (round-9 proven structure) ----------------
// Warp w owns n-tiles {2w, 2w+1} (gate rows 16w..16w+15) x MT m-tiles (tokens).
template <int K16, int MT>
__device__ __forceinline__ void lstm_layer_mma(
    uint32_t inA, int istride, uint32_t outH,
    const uint2* __restrict__ frag,
    const float* __restrict__ bi, const float* __restrict__ bh,
    int w, int lane)
{
    const int gid = lane >> 2, tig = lane & 3;
    const uint32_t rowoff = (uint32_t)((lane & 15) * istride + ((lane & 16) ? 16 : 0));
    float carry[MT][2][4];

#pragma unroll
    for (int s = 0; s < 3; s++) {
        const int RB = (s == 0) ? 0 : (s == 1) ? 256 : 384;
        float acc[MT][2][4];
#pragma unroll
        for (int m = 0; m < MT; m++)
#pragma unroll
            for (int n2 = 0; n2 < 2; n2++)
#pragma unroll
                for (int j = 0; j < 4; j++) acc[m][n2][j] = 0.f;

#pragma unroll
        for (int k = 0; k < K16; k++) {
            uint a[MT][4];
#pragma unroll
            for (int m = 0; m < MT; m++)
                ldsm4(a[m], inA + (uint32_t)(m * 16 * istride + k * 32) + rowoff);
#pragma unroll
            for (int n2 = 0; n2 < 2; n2++) {
                uint2 b = __ldg(&frag[(((s * 16) + (2 * w + n2)) * K16 + k) * 32 + lane]);
#pragma unroll
                for (int m = 0; m < MT; m++) mma16816(acc[m][n2], a[m], b.x, b.y);
            }
        }

#pragma unroll
        for (int n2 = 0; n2 < 2; n2++) {
            const int col0 = (2 * w + n2) * 8 + tig * 2;
            const float b0 = bi[RB + col0] + bh[RB + col0];
            const float b1 = bi[RB + col0 + 1] + bh[RB + col0 + 1];
#pragma unroll
            for (int m = 0; m < MT; m++) {
                float v0 = acc[m][n2][0] + b0;
                float v1 = acc[m][n2][1] + b1;
                float v2 = acc[m][n2][2] + b0;
                float v3 = acc[m][n2][3] + b1;
                if (s == 0) {
                    carry[m][n2][0] = sigm(v0); carry[m][n2][1] = sigm(v1);
                    carry[m][n2][2] = sigm(v2); carry[m][n2][3] = sigm(v3);
                } else if (s == 1) {
                    carry[m][n2][0] *= tanh_ap(v0); carry[m][n2][1] *= tanh_ap(v1);
                    carry[m][n2][2] *= tanh_ap(v2); carry[m][n2][3] *= tanh_ap(v3);
                } else {
                    const int tok0 = m * 16 + gid;
                    float h0 = sigm(v0) * tanh_ap(carry[m][n2][0]);
                    float h1 = sigm(v1) * tanh_ap(carry[m][n2][1]);
                    float h2 = sigm(v2) * tanh_ap(carry[m][n2][2]);
                    float h3 = sigm(v3) * tanh_ap(carry[m][n2][3]);
                    sts32(outH + tok0 * 272 + col0 * 2, pack_bf2(h0, h1));
                    sts32(outH + (tok0 + 8) * 272 + col0 * 2, pack_bf2(h2, h3));
                }
            }
        }
    }
}

template <int MT>
__device__ __forceinline__ void trace_compute(
    char* smc, uint32_t sb, int w, int lane,
    const float* __restrict__ bi1, const float* __restrict__ bh1,
    const float* __restrict__ bi2, const float* __restrict__ bh2,
    const float* __restrict__ bp1, const float* __restrict__ wp2)
{
    const int gid = lane >> 2, tig = lane & 3;

    lstm_layer_mma<4, MT>(sb + S_X, 144, sb + S_H1, g_fw1, bi1, bh1, w, lane);
    __syncthreads();
    lstm_layer_mma<8, MT>(sb + S_H1, 272, sb + S_H2, g_fw2, bi2, bh2, w, lane);
    __syncthreads();

    // ---- MLP energy GEMM: D[MT*16 tok][64 p], warp w owns n-tile w ----
    float acc[MT][4];
#pragma unroll
    for (int m = 0; m < MT; m++)
#pragma unroll
        for (int j = 0; j < 4; j++) acc[m][j] = 0.f;
    const uint32_t rowoff = (uint32_t)((lane & 15) * 272 + ((lane & 16) ? 16 : 0));
#pragma unroll
    for (int k = 0; k < 8; k++) {
        uint a[MT][4];
#pragma unroll
        for (int m = 0; m < MT; m++)
            ldsm4(a[m], sb + S_H2 + (uint32_t)(m * 16 * 272 + k * 32) + rowoff);
        uint2 b = __ldg(&g_fwp[(w * 8 + k) * 32 + lane]);
#pragma unroll
        for (int m = 0; m < MT; m++) mma16816(acc[m], a[m], b.x, b.y);
    }
    // contrib[tok][p] = relu(v + bp1[p]) * wp2[p]  (h1 buffer reused as cbuf)
    const int p0 = w * 8 + tig * 2;
    const float bb0 = bp1[p0], bb1 = bp1[p0 + 1];
    const float w20 = wp2[p0], w21 = wp2[p0 + 1];
    __syncthreads();   // all h1 reads done
#pragma unroll
    for (int m = 0; m < MT; m++) {
        const int tok0 = m * 16 + gid;
        float v0 = fmaxf(acc[m][0] + bb0, 0.f) * w20;
        float v1 = fmaxf(acc[m][1] + bb1, 0.f) * w21;
        float v2 = fmaxf(acc[m][2] + bb0, 0.f) * w20;
        float v3 = fmaxf(acc[m][3] + bb1, 0.f) * w21;
        sts64f(sb + CBUF + tok0 * 272 + p0 * 4, v0, v1);
        sts64f(sb + CBUF + (tok0 + 8) * 272 + p0 * 4, v2, v3);
    }
}

__global__ __launch_bounds__(256, 2) void fused_mma_kernel(
    const float* __restrict__ emb,
    const float* __restrict__ bi1, const float* __restrict__ bh1,
    const float* __restrict__ bi2, const float* __restrict__ bh2,
    const float* __restrict__ bp1, const float* __restrict__ bp2,
    const float* __restrict__ wp2,
    const int* __restrict__ traces, const int* __restrict__ lengths)
{
    extern __shared__ char smc[];
    const int tid = threadIdx.x, w = tid >> 5, lane = tid & 31;
    const int trace = g_perm[blockIdx.x];    // mt-descending schedule
    const uint32_t sb = smem_u32(smc);
    const int len = lengths[trace];
    const int mt = (len + 15) >> 4;

    // ---- gather X -> bf16 smem, only the mt*16 tokens that get consumed ----
    {
        int tok = tid >> 2, seg = tid & 3;
        if (tok < (mt << 4)) {
            int id = traces[trace * LSEQ + tok];
            const float4* s = (const float4*)(emb + id * 64 + seg * 16);
            float4 f0 = s[0], f1 = s[1], f2 = s[2], f3 = s[3];
            uint4 c0, c1;
            c0.x = pack_bf2(f0.x, f0.y); c0.y = pack_bf2(f0.z, f0.w);
            c0.z = pack_bf2(f1.x, f1.y); c0.w = pack_bf2(f1.z, f1.w);
            c1.x = pack_bf2(f2.x, f2.y); c1.y = pack_bf2(f2.z, f2.w);
            c1.z = pack_bf2(f3.x, f3.y); c1.w = pack_bf2(f3.z, f3.w);
            *(uint4*)(smc + S_X + tok * 144 + seg * 32) = c0;
            *(uint4*)(smc + S_X + tok * 144 + seg * 32 + 16) = c1;
        }
    }
    __syncthreads();

    // ---- length-specialized LSTM + MLP (only m-tiles covering len) ----
    switch (mt) {
        case 1: trace_compute<1>(smc, sb, w, lane, bi1, bh1, bi2, bh2, bp1, wp2); break;
        case 2: trace_compute<2>(smc, sb, w, lane, bi1, bh1, bi2, bh2, bp1, wp2); break;
        case 3: trace_compute<3>(smc, sb, w, lane, bi1, bh1, bi2, bh2, bp1, wp2); break;
        default: trace_compute<4>(smc, sb, w, lane, bi1, bh1, bi2, bh2, bp1, wp2); break;
    }
    __syncthreads();

    // ---- energy reduce over p (float4 loads; only valid tokens) ----
    float* E = (float*)(smc + S_E);
    if (tid < len) {
        const float4* row4 = (const float4*)(smc + CBUF + tid * 272);
        float4 t0 = row4[0];
        float s = t0.x + t0.y + t0.z + t0.w;
#pragma unroll
        for (int p4 = 1; p4 < 16; p4++) {
            float4 v = row4[p4];
            s += v.x + v.y + v.z + v.w;
        }
        E[tid] = s + bp2[0];
    }
    __syncthreads();

    // ---- masked softmax (warp 0) ----
    if (tid < 32) {
        float v0 = (tid      < len) ? E[tid]      : -1e30f;
        float v1 = (tid + 32 < len) ? E[tid + 32] : -1e30f;
        float mx = fmaxf(v0, v1);
#pragma unroll
        for (int o = 16; o > 0; o >>= 1) mx = fmaxf(mx, __shfl_xor_sync(~0u, mx, o));
        float e0 = __expf(v0 - mx), e1 = __expf(v1 - mx);
        float ss = e0 + e1;
#pragma unroll
        for (int o = 16; o > 0; o >>= 1) ss += __shfl_xor_sync(~0u, ss, o);
        float inv = __fdividef(1.f, ss);
        E[tid] = e0 * inv; E[tid + 32] = e1 * inv;
    }
    __syncthreads();

    // ---- weighted sum over valid positions (thread = 2 dims, bf16x2 word) ----
    if (tid < 64) {
        float ax = 0.f, ay = 0.f;
#pragma unroll 4
        for (int l = 0; l < len; l++) {
            uint hw = lds32(sb + S_H2 + l * 272 + tid * 4);
            __nv_bfloat162 hv = *reinterpret_cast<__nv_bfloat162*>(&hw);
            float e = E[l];
            ax = fmaf(e, __bfloat162float(hv.x), ax);
            ay = fmaf(e, __bfloat162float(hv.y), ay);
        }
        g_trace_emb[trace * HSZ + 2 * tid]     = ax;
        g_trace_emb[trace * HSZ + 2 * tid + 1] = ay;
    }
}

// ---------------- deterministic reduction + output matvec (round-9 proven) ----
// Stage 1: 64 blocks x 128 threads, each sums 64 traces.
__global__ __launch_bounds__(128) void reduce_part_kernel() {
    const int b = blockIdx.x, t = threadIdx.x;
    float s = 0.f;
    const int tr0 = b * (TRACES / RBLK);
#pragma unroll 8
    for (int i = 0; i < TRACES / RBLK; i++)
        s += g_trace_emb[(tr0 + i) * HSZ + t];
    g_partial[b * HSZ + t] = s;
}

// Stage 2: 1024 threads. 8 groups of 8 partials each; matvec 8 threads/row.
__global__ __launch_bounds__(1024) void reduce_out_kernel(
    const float* __restrict__ Wout, const float* __restrict__ bout,
    float* __restrict__ out)
{
    __shared__ float sq[1024];
    __shared__ float sfinal[HSZ];
    const int tid = threadIdx.x;
    const int q = tid >> 7, h = tid & 127;
    float s = 0.f;
#pragma unroll
    for (int i = 0; i < RBLK / 8; i++)
        s += g_partial[(q * (RBLK / 8) + i) * HSZ + h];
    sq[tid] = s;
    __syncthreads();
    if (tid < HSZ) {
        float t2 = 0.f;
#pragma unroll
        for (int g = 0; g < 8; g++) t2 += sq[g * 128 + tid];
        sfinal[tid] = t2;
    }
    __syncthreads();
    {   // matvec: 8 threads per output row, 16 k each
        const int r = tid >> 3, seg = tid & 7;
        float o = 0.f;
#pragma unroll
        for (int k = 0; k < 16; k++)
            o = fmaf(__ldg(&Wout[r * HSZ + seg * 16 + k]), sfinal[seg * 16 + k], o);
        o += __shfl_down_sync(0xffffffffu, o, 4, 8);
        o += __shfl_down_sync(0xffffffffu, o, 2, 8);
        o += __shfl_down_sync(0xffffffffu, o, 1, 8);
        if (seg == 0) out[r] = o + bout[r];
    }
}

extern "C" void kernel_launch(void* const* d_in, const int* in_sizes, int n_in,
                              void* d_out, int out_size) {
    const float* emb    = (const float*)d_in[0];
    const float* W1     = (const float*)d_in[1];
    const float* bi1    = (const float*)d_in[3];
    const float* bh1    = (const float*)d_in[4];
    const float* W2     = (const float*)d_in[5];
    const float* bi2    = (const float*)d_in[7];
    const float* bh2    = (const float*)d_in[8];
    const float* Wp1    = (const float*)d_in[9];
    const float* bp1    = (const float*)d_in[10];
    const float* Wp2    = (const float*)d_in[11];
    const float* bp2    = (const float*)d_in[12];
    const float* Wout   = (const float*)d_in[13];
    const float* bout   = (const float*)d_in[14];
    const int*   traces = (const int*)d_in[15];
    const int*   lens   = (const int*)d_in[16];

    cudaFuncSetAttribute(fused_mma_kernel,
                         cudaFuncAttributeMaxDynamicSharedMemorySize, SMEM_BYTES);

    init_frags<<<81, 256>>>(W1, W2, Wp1, lens);
    fused_mma_kernel<<<TRACES, 256, SMEM_BYTES>>>(
        emb, bi1, bh1, bi2, bh2, bp1, bp2, Wp2, traces, lens);
    reduce_part_kernel<<<RBLK, 128>>>();
    reduce_out_kernel<<<1, 1024>>>(Wout, bout, (float*)d_out);
}

// round 17
// speedup vs baseline: 1.6350x; 1.0532x over previous
#include <cuda_runtime.h>
#include <cuda_bf16.h>
#include <cstdint>

#define TRACES 4096
#define LSEQ   64
#define HSZ    128

typedef unsigned int uint;
typedef unsigned long long ull;

// Fixed-point scale for deterministic integer accumulation.
#define FPSCALE     4398046511104.0f          // 2^42
#define INV_FPSCALE 2.2737367544323206e-13f   // 2^-42

// ---- device scratch (static globals, no allocation) ----
__device__ uint2 g_fw1[3 * 16 * 4 * 32];   // [gate][ntile][k16][lane]
__device__ uint2 g_fw2[3 * 16 * 8 * 32];
__device__ uint2 g_fwp[8 * 8 * 32];
__device__ ull   g_acc[HSZ];               // fixed-point trace-emb accumulator

// ---- smem byte layout (round-9 proven; stride 272 = 256 data + 16 pad) ----
#define S_X    0            // X  [64 tok][72 bf16]  stride 144B (9216B)
#define S_H1   9216         // h1 [64][136 bf16]     stride 272B (17408B)
#define S_H2   26624        // h2 [64][136 bf16]     stride 272B (17408B)
#define S_E    44032        // 64 floats
#define SMEM_BYTES 44288
#define CBUF   S_H1         // MLP contrib reuse: [64 tok][68 f32] stride 272B

__device__ __forceinline__ uint32_t smem_u32(const void* p) {
    uint32_t a;
    asm("{ .reg .u64 t; cvta.to.shared.u64 t, %1; cvt.u32.u64 %0, t; }" : "=r"(a) : "l"(p));
    return a;
}
__device__ __forceinline__ uint lds32(uint32_t a) {
    uint v; asm volatile("ld.shared.b32 %0, [%1];" : "=r"(v) : "r"(a)); return v;
}
__device__ __forceinline__ void sts32(uint32_t a, uint v) {
    asm volatile("st.shared.b32 [%0], %1;" :: "r"(a), "r"(v));
}
__device__ __forceinline__ void sts64f(uint32_t a, float x, float y) {
    asm volatile("st.shared.v2.f32 [%0], {%1, %2};" :: "r"(a), "f"(x), "f"(y));
}
__device__ __forceinline__ void ldsm4(uint r[4], uint32_t addr) {
    asm volatile("ldmatrix.sync.aligned.m8n8.x4.shared.b16 {%0,%1,%2,%3}, [%4];"
                 : "=r"(r[0]), "=r"(r[1]), "=r"(r[2]), "=r"(r[3]) : "r"(addr));
}
__device__ __forceinline__ void mma16816(float c[4], const uint a[4], uint b0, uint b1) {
    asm volatile(
        "mma.sync.aligned.m16n8k16.row.col.f32.bf16.bf16.f32 "
        "{%0,%1,%2,%3}, {%4,%5,%6,%7}, {%8,%9}, {%0,%1,%2,%3};"
        : "+f"(c[0]), "+f"(c[1]), "+f"(c[2]), "+f"(c[3])
        : "r"(a[0]), "r"(a[1]), "r"(a[2]), "r"(a[3]), "r"(b0), "r"(b1));
}
__device__ __forceinline__ float tanh_ap(float x) {
    float y; asm("tanh.approx.f32 %0, %1;" : "=f"(y) : "f"(x)); return y;
}
__device__ __forceinline__ float sigm(float x) {
    return fmaf(0.5f, tanh_ap(0.5f * x), 0.5f);
}
__device__ __forceinline__ uint pack_bf2(float a, float b) {
    __nv_bfloat162 t = __float22bfloat162_rn(make_float2(a, b));
    return *reinterpret_cast<uint*>(&t);
}

// ---------------- init: pack W frags + zero accumulator (per launch/replay) ----
// B frag (m16n8k16, row.col): b0 = {B[k0][n], B[k0+1][n]}, b1 = {+8}, with
// n = ntile*8 + (lane>>2), k0 = k16*16 + (lane&3)*2.  Gate rows: i=0, c=256, o=384.
__global__ void init_frags(const float* __restrict__ W1, const float* __restrict__ W2,
                           const float* __restrict__ Wp1) {
    if (blockIdx.x == 80) {                 // zero fixed-point accumulator
        if (threadIdx.x < HSZ) g_acc[threadIdx.x] = 0ULL;
        return;
    }
    int idx = blockIdx.x * 256 + threadIdx.x;
    const int GR[3] = {0, 256, 384};
    if (idx < 6144) {                       // L1: [3][16][4][32], K=64
        int lane = idx & 31, k16 = (idx >> 5) & 3, nt = (idx >> 7) & 15, g = idx >> 11;
        int n = nt * 8 + (lane >> 2), k0 = k16 * 16 + (lane & 3) * 2;
        const float* r = W1 + (GR[g] + n) * 64;
        g_fw1[idx] = make_uint2(pack_bf2(r[k0], r[k0 + 1]),
                                pack_bf2(r[k0 + 8], r[k0 + 9]));
    } else if (idx < 18432) {               // L2: [3][16][8][32], K=128
        int j = idx - 6144;
        int lane = j & 31, k16 = (j >> 5) & 7, nt = (j >> 8) & 15, g = j >> 12;
        int n = nt * 8 + (lane >> 2), k0 = k16 * 16 + (lane & 3) * 2;
        const float* r = W2 + (GR[g] + n) * 128;
        g_fw2[j] = make_uint2(pack_bf2(r[k0], r[k0 + 1]),
                              pack_bf2(r[k0 + 8], r[k0 + 9]));
    } else if (idx < 20480) {               // MLP: [8][8][32], K=128, R=64
        int j = idx - 18432;
        int lane = j & 31, k16 = (j >> 5) & 7, nt = j >> 8;
        int n = nt * 8 + (lane >> 2), k0 = k16 * 16 + (lane & 3) * 2;
        const float* r = Wp1 + n * 128;
        g_fwp[j] = make_uint2(pack_bf2(r[k0], r[k0 + 1]),
                              pack_bf2(r[k0 + 8], r[k0 + 9]));
    }
}

// ---------------- fused per-trace kernel (round-9 proven structure) ----------------
// Warp w owns n-tiles {2w, 2w+1} (gate rows 16w..16w+15) x MT m-tiles (tokens).
template <int K16, int MT>
__device__ __forceinline__ void lstm_layer_mma(
    uint32_t inA, int istride, uint32_t outH,
    const uint2* __restrict__ frag,
    const float* __restrict__ bi, const float* __restrict__ bh,
    int w, int lane)
{
    const int gid = lane >> 2, tig = lane & 3;
    const uint32_t rowoff = (uint32_t)((lane & 15) * istride + ((lane & 16) ? 16 : 0));
    float carry[MT][2][4];

#pragma unroll
    for (int s = 0; s < 3; s++) {
        const int RB = (s == 0) ? 0 : (s == 1) ? 256 : 384;
        float acc[MT][2][4];
#pragma unroll
        for (int m = 0; m < MT; m++)
#pragma unroll
            for (int n2 = 0; n2 < 2; n2++)
#pragma unroll
                for (int j = 0; j < 4; j++) acc[m][n2][j] = 0.f;

#pragma unroll
        for (int k = 0; k < K16; k++) {
            uint a[MT][4];
#pragma unroll
            for (int m = 0; m < MT; m++)
                ldsm4(a[m], inA + (uint32_t)(m * 16 * istride + k * 32) + rowoff);
#pragma unroll
            for (int n2 = 0; n2 < 2; n2++) {
                uint2 b = __ldg(&frag[(((s * 16) + (2 * w + n2)) * K16 + k) * 32 + lane]);
#pragma unroll
                for (int m = 0; m < MT; m++) mma16816(acc[m][n2], a[m], b.x, b.y);
            }
        }

#pragma unroll
        for (int n2 = 0; n2 < 2; n2++) {
            const int col0 = (2 * w + n2) * 8 + tig * 2;
            const float b0 = bi[RB + col0] + bh[RB + col0];
            const float b1 = bi[RB + col0 + 1] + bh[RB + col0 + 1];
#pragma unroll
            for (int m = 0; m < MT; m++) {
                float v0 = acc[m][n2][0] + b0;
                float v1 = acc[m][n2][1] + b1;
                float v2 = acc[m][n2][2] + b0;
                float v3 = acc[m][n2][3] + b1;
                if (s == 0) {
                    carry[m][n2][0] = sigm(v0); carry[m][n2][1] = sigm(v1);
                    carry[m][n2][2] = sigm(v2); carry[m][n2][3] = sigm(v3);
                } else if (s == 1) {
                    carry[m][n2][0] *= tanh_ap(v0); carry[m][n2][1] *= tanh_ap(v1);
                    carry[m][n2][2] *= tanh_ap(v2); carry[m][n2][3] *= tanh_ap(v3);
                } else {
                    const int tok0 = m * 16 + gid;
                    float h0 = sigm(v0) * tanh_ap(carry[m][n2][0]);
                    float h1 = sigm(v1) * tanh_ap(carry[m][n2][1]);
                    float h2 = sigm(v2) * tanh_ap(carry[m][n2][2]);
                    float h3 = sigm(v3) * tanh_ap(carry[m][n2][3]);
                    sts32(outH + tok0 * 272 + col0 * 2, pack_bf2(h0, h1));
                    sts32(outH + (tok0 + 8) * 272 + col0 * 2, pack_bf2(h2, h3));
                }
            }
        }
    }
}

template <int MT>
__device__ __forceinline__ void trace_compute(
    char* smc, uint32_t sb, int w, int lane,
    const float* __restrict__ bi1, const float* __restrict__ bh1,
    const float* __restrict__ bi2, const float* __restrict__ bh2,
    const float* __restrict__ bp1, const float* __restrict__ wp2)
{
    const int gid = lane >> 2, tig = lane & 3;

    lstm_layer_mma<4, MT>(sb + S_X, 144, sb + S_H1, g_fw1, bi1, bh1, w, lane);
    __syncthreads();
    lstm_layer_mma<8, MT>(sb + S_H1, 272, sb + S_H2, g_fw2, bi2, bh2, w, lane);
    __syncthreads();

    // ---- MLP energy GEMM: D[MT*16 tok][64 p], warp w owns n-tile w ----
    float acc[MT][4];
#pragma unroll
    for (int m = 0; m < MT; m++)
#pragma unroll
        for (int j = 0; j < 4; j++) acc[m][j] = 0.f;
    const uint32_t rowoff = (uint32_t)((lane & 15) * 272 + ((lane & 16) ? 16 : 0));
#pragma unroll
    for (int k = 0; k < 8; k++) {
        uint a[MT][4];
#pragma unroll
        for (int m = 0; m < MT; m++)
            ldsm4(a[m], sb + S_H2 + (uint32_t)(m * 16 * 272 + k * 32) + rowoff);
        uint2 b = __ldg(&g_fwp[(w * 8 + k) * 32 + lane]);
#pragma unroll
        for (int m = 0; m < MT; m++) mma16816(acc[m], a[m], b.x, b.y);
    }
    // contrib[tok][p] = relu(v + bp1[p]) * wp2[p]  (h1 buffer reused as cbuf)
    const int p0 = w * 8 + tig * 2;
    const float bb0 = bp1[p0], bb1 = bp1[p0 + 1];
    const float w20 = wp2[p0], w21 = wp2[p0 + 1];
    __syncthreads();   // all h1 reads done
#pragma unroll
    for (int m = 0; m < MT; m++) {
        const int tok0 = m * 16 + gid;
        float v0 = fmaxf(acc[m][0] + bb0, 0.f) * w20;
        float v1 = fmaxf(acc[m][1] + bb1, 0.f) * w21;
        float v2 = fmaxf(acc[m][2] + bb0, 0.f) * w20;
        float v3 = fmaxf(acc[m][3] + bb1, 0.f) * w21;
        sts64f(sb + CBUF + tok0 * 272 + p0 * 4, v0, v1);
        sts64f(sb + CBUF + (tok0 + 8) * 272 + p0 * 4, v2, v3);
    }
}

__global__ __launch_bounds__(256, 2) void fused_mma_kernel(
    const float* __restrict__ emb,
    const float* __restrict__ bi1, const float* __restrict__ bh1,
    const float* __restrict__ bi2, const float* __restrict__ bh2,
    const float* __restrict__ bp1, const float* __restrict__ bp2,
    const float* __restrict__ wp2,
    const int* __restrict__ traces, const int* __restrict__ lengths)
{
    extern __shared__ char smc[];
    const int tid = threadIdx.x, w = tid >> 5, lane = tid & 31;
    const int trace = blockIdx.x;
    const uint32_t sb = smem_u32(smc);
    const int len = lengths[trace];
    const int mt = (len + 15) >> 4;

    // ---- gather X -> bf16 smem, only the mt*16 tokens that get consumed ----
    {
        int tok = tid >> 2, seg = tid & 3;
        if (tok < (mt << 4)) {
            int id = traces[trace * LSEQ + tok];
            const float4* s = (const float4*)(emb + id * 64 + seg * 16);
            float4 f0 = s[0], f1 = s[1], f2 = s[2], f3 = s[3];
            uint4 c0, c1;
            c0.x = pack_bf2(f0.x, f0.y); c0.y = pack_bf2(f0.z, f0.w);
            c0.z = pack_bf2(f1.x, f1.y); c0.w = pack_bf2(f1.z, f1.w);
            c1.x = pack_bf2(f2.x, f2.y); c1.y = pack_bf2(f2.z, f2.w);
            c1.z = pack_bf2(f3.x, f3.y); c1.w = pack_bf2(f3.z, f3.w);
            *(uint4*)(smc + S_X + tok * 144 + seg * 32) = c0;
            *(uint4*)(smc + S_X + tok * 144 + seg * 32 + 16) = c1;
        }
    }
    __syncthreads();

    // ---- length-specialized LSTM + MLP (only m-tiles covering len) ----
    switch (mt) {
        case 1: trace_compute<1>(smc, sb, w, lane, bi1, bh1, bi2, bh2, bp1, wp2); break;
        case 2: trace_compute<2>(smc, sb, w, lane, bi1, bh1, bi2, bh2, bp1, wp2); break;
        case 3: trace_compute<3>(smc, sb, w, lane, bi1, bh1, bi2, bh2, bp1, wp2); break;
        default: trace_compute<4>(smc, sb, w, lane, bi1, bh1, bi2, bh2, bp1, wp2); break;
    }
    __syncthreads();

    // ---- energy reduce over p (float4 loads; only valid tokens) ----
    float* E = (float*)(smc + S_E);
    if (tid < len) {
        const float4* row4 = (const float4*)(smc + CBUF + tid * 272);
        float4 t0 = row4[0];
        float s = t0.x + t0.y + t0.z + t0.w;
#pragma unroll
        for (int p4 = 1; p4 < 16; p4++) {
            float4 v = row4[p4];
            s += v.x + v.y + v.z + v.w;
        }
        E[tid] = s + bp2[0];
    }
    __syncthreads();

    // ---- masked softmax (warp 0) ----
    if (tid < 32) {
        float v0 = (tid      < len) ? E[tid]      : -1e30f;
        float v1 = (tid + 32 < len) ? E[tid + 32] : -1e30f;
        float mx = fmaxf(v0, v1);
#pragma unroll
        for (int o = 16; o > 0; o >>= 1) mx = fmaxf(mx, __shfl_xor_sync(~0u, mx, o));
        float e0 = __expf(v0 - mx), e1 = __expf(v1 - mx);
        float ss = e0 + e1;
#pragma unroll
        for (int o = 16; o > 0; o >>= 1) ss += __shfl_xor_sync(~0u, ss, o);
        float inv = __fdividef(1.f, ss);
        E[tid] = e0 * inv; E[tid + 32] = e1 * inv;
    }
    __syncthreads();

    // ---- weighted sum + DETERMINISTIC fixed-point accumulation over traces ----
    // Integer atomics commute exactly -> bit-identical output for any block order.
    if (tid < 64) {
        float ax = 0.f, ay = 0.f;
#pragma unroll 4
        for (int l = 0; l < len; l++) {
            uint hw = lds32(sb + S_H2 + l * 272 + tid * 4);
            __nv_bfloat162 hv = *reinterpret_cast<__nv_bfloat162*>(&hw);
            float e = E[l];
            ax = fmaf(e, __bfloat162float(hv.x), ax);
            ay = fmaf(e, __bfloat162float(hv.y), ay);
        }
        long long qx = llrintf(ax * FPSCALE);
        long long qy = llrintf(ay * FPSCALE);
        atomicAdd(&g_acc[2 * tid],     (ull)qx);   // two's-complement add
        atomicAdd(&g_acc[2 * tid + 1], (ull)qy);
    }
}

// ---------------- tiny tail: fixed-point -> float, 128x128 matvec ----------------
__global__ __launch_bounds__(1024) void out_matvec_kernel(
    const float* __restrict__ Wout, const float* __restrict__ bout,
    float* __restrict__ out)
{
    __shared__ float sfinal[HSZ];
    const int tid = threadIdx.x;
    if (tid < HSZ)
        sfinal[tid] = (float)((long long)g_acc[tid]) * INV_FPSCALE;
    __syncthreads();
    {   // matvec: 8 threads per output row, 16 k each
        const int r = tid >> 3, seg = tid & 7;
        float o = 0.f;
#pragma unroll
        for (int k = 0; k < 16; k++)
            o = fmaf(__ldg(&Wout[r * HSZ + seg * 16 + k]), sfinal[seg * 16 + k], o);
        o += __shfl_down_sync(0xffffffffu, o, 4, 8);
        o += __shfl_down_sync(0xffffffffu, o, 2, 8);
        o += __shfl_down_sync(0xffffffffu, o, 1, 8);
        if (seg == 0) out[r] = o + bout[r];
    }
}

extern "C" void kernel_launch(void* const* d_in, const int* in_sizes, int n_in,
                              void* d_out, int out_size) {
    const float* emb    = (const float*)d_in[0];
    const float* W1     = (const float*)d_in[1];
    const float* bi1    = (const float*)d_in[3];
    const float* bh1    = (const float*)d_in[4];
    const float* W2     = (const float*)d_in[5];
    const float* bi2    = (const float*)d_in[7];
    const float* bh2    = (const float*)d_in[8];
    const float* Wp1    = (const float*)d_in[9];
    const float* bp1    = (const float*)d_in[10];
    const float* Wp2    = (const float*)d_in[11];
    const float* bp2    = (const float*)d_in[12];
    const float* Wout   = (const float*)d_in[13];
    const float* bout   = (const float*)d_in[14];
    const int*   traces = (const int*)d_in[15];
    const int*   lens   = (const int*)d_in[16];

    cudaFuncSetAttribute(fused_mma_kernel,
                         cudaFuncAttributeMaxDynamicSharedMemorySize, SMEM_BYTES);

    init_frags<<<81, 256>>>(W1, W2, Wp1);   // also zeroes g_acc each replay
    fused_mma_kernel<<<TRACES, 256, SMEM_BYTES>>>(
        emb, bi1, bh1, bi2, bh2, bp1, bp2, Wp2, traces, lens);
    out_matvec_kernel<<<1, 1024>>>(Wout, bout, (float*)d_out);
}